// round 6
// baseline (speedup 1.0000x reference)
#include <cuda_runtime.h>
#include <math.h>
#include <stdint.h>

// ---------------------------------------------------------------------------
// GridFeatureToPointGraphConv — R6: B2 half-row split (8 LDS.128/k, pair-shfl
// combine, bank-rotated half-1 chunks), B1 back to plain LDG gathers (R4).
// Numerics: componentwise identical; dot reassociation only (~1e-7).
// ---------------------------------------------------------------------------

#define RES 48
#define NGRID (RES*RES*RES)      // 110592
#define NPTS 65536
#define HID 64
#define KNN 16

typedef unsigned long long u64;

__device__ float g_Gpre[NGRID * HID];   // 28.3 MB scratch (L2-resident)
__device__ u64   g_W2p[32 * 32];        // {W2[2i][o], W2[2i+1][o]} pairs
__device__ u64   g_W3p[16 * 32];        // {W3[2i][o], W3[2i+1][o]} pairs

// ---- f32x2 helpers -------------------------------------------------------
__device__ __forceinline__ u64 pack2(float lo, float hi) {
    u64 r; asm("mov.b64 %0, {%1,%2};" : "=l"(r) : "f"(lo), "f"(hi)); return r;
}
__device__ __forceinline__ void unpack2(u64 v, float& lo, float& hi) {
    asm("mov.b64 {%0,%1}, %2;" : "=f"(lo), "=f"(hi) : "l"(v));
}
__device__ __forceinline__ u64 fma2(u64 a, u64 b, u64 c) {
    u64 d; asm("fma.rn.f32x2 %0, %1, %2, %3;" : "=l"(d) : "l"(a), "l"(b), "l"(c)); return d;
}
__device__ __forceinline__ u64 mul2(u64 a, u64 b) {
    u64 d; asm("mul.rn.f32x2 %0, %1, %2;" : "=l"(d) : "l"(a), "l"(b)); return d;
}
__device__ __forceinline__ u64 add2(u64 a, u64 b) {
    u64 d; asm("add.rn.f32x2 %0, %1, %2;" : "=l"(d) : "l"(a), "l"(b)); return d;
}
__device__ __forceinline__ float ex2f(float x) {
    float r; asm("ex2.approx.f32 %0, %1;" : "=f"(r) : "f"(x)); return r;
}
__device__ __forceinline__ float rcpf(float x) {
    float r; asm("rcp.approx.f32 %0, %1;" : "=f"(r) : "f"(x)); return r;
}

// gelu_tanh(x) == x / (1 + e^{-p}), p = 1.5957691216x + 0.07135481681x^3
__device__ __forceinline__ float gelu_fast(float x) {
    float u = x * x;
    float w = __fmaf_rn(0.07135481681f, u, 1.5957691216f);
    float p = x * w;
    float e = __expf(-p);
    return __fdividef(x, 1.0f + e);
}

// paired gelu: componentwise identical rounding to gelu_fast
__device__ __forceinline__ u64 gelu2(u64 x, u64 C0, u64 C1, u64 NL2E, u64 ONE2) {
    u64 u = mul2(x, x);
    u64 w = fma2(u, C0, C1);
    u64 p = mul2(x, w);
    u64 m = mul2(p, NL2E);
    float m0, m1; unpack2(m, m0, m1);
    u64 e = pack2(ex2f(m0), ex2f(m1));
    u64 den = add2(ONE2, e);
    float d0, d1; unpack2(den, d0, d1);
    u64 r = pack2(rcpf(d0), rcpf(d1));
    return mul2(x, r);
}

// ---------------------------------------------------------------------------
// Kernel 1: Gpre[g][i] = sum_c grid_features[g][c] * W1[c][i]   (rows 0..31)
//           + pack W2/W3 pair tables (block 0)
// ---------------------------------------------------------------------------
__global__ __launch_bounds__(256) void gpre_kernel(const float* __restrict__ gf,
                                                   const float* __restrict__ W1,
                                                   const float* __restrict__ W2,
                                                   const float* __restrict__ W3) {
    __shared__ float W1s[32 * 64];
    __shared__ float gfs[4 * 32];
    int tid = threadIdx.x;
    for (int t = tid; t < 32 * 64; t += 256) W1s[t] = W1[t];

    if (blockIdx.x == 0) {
        for (int j = tid; j < 32 * 32; j += 256) {
            int i = j >> 5, o = j & 31;
            g_W2p[j] = pack2(W2[(2 * i) * 32 + o], W2[(2 * i + 1) * 32 + o]);
        }
        for (int j = tid; j < 16 * 32; j += 256) {
            int i = j >> 5, o = j & 31;
            g_W3p[j] = pack2(W3[(2 * i) * 32 + o], W3[(2 * i + 1) * 32 + o]);
        }
    }

    int i = tid & 63;
    int v = tid >> 6;
    int base = blockIdx.x * 32;

    for (int it = 0; it < 8; ++it) {
        int g = base + it * 4;
        __syncthreads();
        if (tid < 128) gfs[tid] = gf[(size_t)g * 32 + tid];
        __syncthreads();
        float acc = 0.0f;
        #pragma unroll
        for (int c = 0; c < 32; ++c)
            acc = fmaf(gfs[v * 32 + c], W1s[c * 64 + i], acc);
        g_Gpre[(size_t)g * 64 + (size_t)tid] = acc;
    }
}

// ---------------------------------------------------------------------------
// Candidate distance, matching reference expansion: qq - 2*(q.p) + pp
// ---------------------------------------------------------------------------
__device__ __forceinline__ float cand_dist(int t, int ix0, int iy0, int iz0,
                                           const float* __restrict__ lins,
                                           float qx, float qy, float qz, float qq) {
    int a = t >> 4, b = (t >> 2) & 3, c = t & 3;
    float px = lins[ix0 + a], py = lins[iy0 + b], pz = lins[iz0 + c];
    float pp = __fadd_rn(__fadd_rn(__fmul_rn(px, px), __fmul_rn(py, py)), __fmul_rn(pz, pz));
    float dot = __fmaf_rn(qz, pz, __fmaf_rn(qy, py, __fmul_rn(qx, px)));
    return __fadd_rn(__fsub_rn(qq, __fadd_rn(dot, dot)), pp);
}

__device__ __forceinline__ unsigned int fmap(float d) {
    unsigned int b = __float_as_uint(d);
    return (b & 0x80000000u) ? ~b : (b | 0x80000000u);
}

__device__ __forceinline__ u64 bitonic_ce(u64 key, int j, bool up, int lane) {
    u64 pk = __shfl_xor_sync(0xffffffffu, key, j);
    bool lower = ((lane & j) == 0);
    u64 mn = (key < pk) ? key : pk;
    u64 mx = (key < pk) ? pk : key;
    return ((lower == up)) ? mn : mx;
}

// ---------------------------------------------------------------------------
// Kernel 2: fused KNN + edge MLP + mean + out MLP. One warp per point.
// ---------------------------------------------------------------------------
__global__ __launch_bounds__(256, 2) void fused_kernel(
    const float* __restrict__ gv,
    const float* __restrict__ pv,
    const float* __restrict__ pf,
    const float* __restrict__ W1,
    const float* __restrict__ b1,
    const float* __restrict__ b2,
    const float* __restrict__ b3,
    float* __restrict__ out)
{
    __shared__ float lins[RES];
    __shared__ __align__(16) float W1s[35 * 64];     // W1 rows 32..66 (self + rel)
    __shared__ float b1s[64];
    __shared__ __align__(8) float b2s[32];
    __shared__ float b3s[32];
    __shared__ __align__(16) float h1s[8][16][64];   // per-warp, per-edge hidden
    __shared__ __align__(16) float aggs[8][32];

    int tid = threadIdx.x;
    for (int t = tid; t < 35 * 64; t += 256) W1s[t] = W1[32 * 64 + t];
    if (tid < 64) b1s[tid] = b1[tid];
    if (tid >= 64 && tid < 96)  b2s[tid - 64] = b2[tid - 64];
    if (tid >= 96 && tid < 128) b3s[tid - 96] = b3[tid - 96];
    if (tid >= 128 && tid < 128 + RES)
        lins[tid - 128] = __fmul_rn(gv[3 * (tid - 128) + 2], 24.0f);
    __syncthreads();

    const int w = tid >> 5;
    const int lane = tid & 31;
    const int p = blockIdx.x * 8 + w;
    const int half = lane >> 4;              // 0: i in [0,32), 1: i in [32,64)
    const int oA = (lane & 15) * 2;          // this lane's two outputs
    // (oB = oA + 1)

    const u64 C0   = pack2(0.07135481681f, 0.07135481681f);
    const u64 C1   = pack2(1.5957691216f, 1.5957691216f);
    const u64 NL2E = pack2(-1.442695041f, -1.442695041f);
    const u64 ONE2 = pack2(1.0f, 1.0f);

    // W2 pairs for this lane's half-range and two outputs.
    // w2A[c] = {W2[i0][oA], W2[i0+1][oA]}, i0 = 2*(16*half + c)
    u64 w2A[16], w2B[16];
    #pragma unroll
    for (int c = 0; c < 16; ++c) {
        w2A[c] = __ldg(&g_W2p[(16 * half + c) * 32 + oA]);
        w2B[c] = __ldg(&g_W2p[(16 * half + c) * 32 + oA + 1]);
    }

    // point coords (scaled)
    float qxu = __ldg(&pv[p * 3 + 0]);
    float qyu = __ldg(&pv[p * 3 + 1]);
    float qzu = __ldg(&pv[p * 3 + 2]);
    float qx = __fmul_rn(qxu, 24.0f);
    float qy = __fmul_rn(qyu, 24.0f);
    float qz = __fmul_rn(qzu, 24.0f);
    float qq = __fadd_rn(__fadd_rn(__fmul_rn(qx, qx), __fmul_rn(qy, qy)), __fmul_rn(qz, qz));

    // per-point layer-1 partial (channels 2*lane, 2*lane+1), packed
    const u64* W1su = reinterpret_cast<const u64*>(W1s);
    u64 pre2 = pack2(b1s[lane * 2], b1s[lane * 2 + 1]);
    {
        const float4* pf4 = reinterpret_cast<const float4*>(pf + (size_t)p * 32);
        #pragma unroll
        for (int c4 = 0; c4 < 8; ++c4) {
            float4 f = __ldg(&pf4[c4]);
            pre2 = fma2(pack2(f.x, f.x), W1su[(c4 * 4 + 0) * 32 + lane], pre2);
            pre2 = fma2(pack2(f.y, f.y), W1su[(c4 * 4 + 1) * 32 + lane], pre2);
            pre2 = fma2(pack2(f.z, f.z), W1su[(c4 * 4 + 2) * 32 + lane], pre2);
            pre2 = fma2(pack2(f.w, f.w), W1su[(c4 * 4 + 3) * 32 + lane], pre2);
        }
    }
    u64 w1rx2 = W1su[32 * 32 + lane];
    u64 w1ry2 = W1su[33 * 32 + lane];
    u64 w1rz2 = W1su[34 * 32 + lane];

    // ---- Phase A: selection via bitonic sort of 64 (d, t) keys ----
    int ix0 = min(max((int)floorf((qxu + 1.0f) * 23.5f) - 1, 0), RES - 4);
    int iy0 = min(max((int)floorf((qyu + 1.0f) * 23.5f) - 1, 0), RES - 4);
    int iz0 = min(max((int)floorf((qzu + 1.0f) * 23.5f) - 1, 0), RES - 4);

    float dA = cand_dist(lane,      ix0, iy0, iz0, lins, qx, qy, qz, qq);
    float dB = cand_dist(lane + 32, ix0, iy0, iz0, lins, qx, qy, qz, qq);
    u64 key0 = ((u64)fmap(dA) << 32) | (unsigned int)lane;
    u64 key1 = ((u64)fmap(dB) << 32) | (unsigned int)(lane + 32);

    #pragma unroll
    for (int ks = 2; ks <= 32; ks <<= 1) {
        bool up0 = ((lane & ks) == 0);
        bool up1 = (((lane + 32) & ks) == 0);
        #pragma unroll
        for (int j = ks >> 1; j > 0; j >>= 1) {
            key0 = bitonic_ce(key0, j, up0, lane);
            key1 = bitonic_ce(key1, j, up1, lane);
        }
    }
    {   // final merge: keep min half, clean 5 levels
        key0 = (key0 < key1) ? key0 : key1;
        #pragma unroll
        for (int j = 16; j > 0; j >>= 1)
            key0 = bitonic_ce(key0, j, true, lane);
    }
    int myt = (int)((unsigned int)key0 & 63u);   // lane k (<16) holds rank-k neighbor

    // ---- Phase B1: edge layer-1 for all 16 edges (LDG gathers, unroll 4) ----
    const u64* Gpreu = reinterpret_cast<const u64*>(g_Gpre);
    u64* h1u = reinterpret_cast<u64*>(&h1s[w][0][0]);
    const int gbase = ix0 * (RES * RES) + iy0 * RES + iz0;
    #pragma unroll 4
    for (int k = 0; k < KNN; ++k) {
        int t = __shfl_sync(0xffffffffu, myt, k);
        int a = t >> 4, b = (t >> 2) & 3, c = t & 3;
        int gm = gbase + a * (RES * RES) + b * RES + c;
        float rx = __fsub_rn(lins[ix0 + a], qx);
        float ry = __fsub_rn(lins[iy0 + b], qy);
        float rz = __fsub_rn(lins[iz0 + c], qz);

        u64 gp = __ldg(&Gpreu[(size_t)gm * 32 + lane]);
        u64 t2 = add2(pre2, gp);
        t2 = fma2(pack2(rx, rx), w1rx2, t2);
        t2 = fma2(pack2(ry, ry), w1ry2, t2);
        t2 = fma2(pack2(rz, rz), w1rz2, t2);
        h1u[k * 32 + lane] = gelu2(t2, C0, C1, NL2E, ONE2);
    }
    __syncwarp();

    // ---- Phase B2: half-row split layer-2 ----
    // Lane loads its half (8 x 16B chunks, half-1 bank-rotated), computes
    // partials for outputs oA, oA+1; pair-exchange with lane^16 completes dots.
    u64 b2pair = reinterpret_cast<const u64*>(b2s)[lane & 15];
    const int rot = half * 4;
    u64 agg2 = pack2(0.0f, 0.0f);
    #pragma unroll 2
    for (int k = 0; k < KNN; ++k) {
        const ulonglong2* hh = reinterpret_cast<const ulonglong2*>(&h1s[w][k][0]);
        u64 accA = pack2(0.0f, 0.0f);
        u64 accB = pack2(0.0f, 0.0f);
        #pragma unroll
        for (int j = 0; j < 8; ++j) {
            int c = (j + rot) & 7;                 // chunk within half
            ulonglong2 hp = hh[half * 8 + c];      // 16B: i-pairs 2c, 2c+1 of half
            accA = fma2(hp.x, w2A[2 * c + 0], accA);
            accA = fma2(hp.y, w2A[2 * c + 1], accA);
            accB = fma2(hp.x, w2B[2 * c + 0], accB);
            accB = fma2(hp.y, w2B[2 * c + 1], accB);
        }
        // combine halves with partner lane (lane ^ 16), same outputs
        accA = add2(accA, __shfl_xor_sync(0xffffffffu, accA, 16));
        accB = add2(accB, __shfl_xor_sync(0xffffffffu, accB, 16));
        float a0, a1, c0, c1;
        unpack2(accA, a0, a1);
        unpack2(accB, c0, c1);
        float bA, bB; unpack2(b2pair, bA, bB);
        u64 acc2 = pack2(__fadd_rn(__fadd_rn(a0, a1), bA),
                         __fadd_rn(__fadd_rn(c0, c1), bB));
        agg2 = add2(agg2, gelu2(acc2, C0, C1, NL2E, ONE2));
    }

    // ---- mean over K, out transform (packed) ----
    u64 HK2 = pack2(0.0625f, 0.0625f);
    agg2 = mul2(agg2, HK2);
    u64* aggsu = reinterpret_cast<u64*>(&aggs[w][0]);
    if (half == 0) aggsu[lane & 15] = agg2;        // lanes 16-31 redundant
    __syncwarp();
    const u64* ag2 = reinterpret_cast<const u64*>(&aggs[w][0]);
    u64 acc2 = pack2(0.0f, 0.0f);
    #pragma unroll
    for (int i2 = 0; i2 < 16; ++i2)
        acc2 = fma2(ag2[i2], __ldg(&g_W3p[i2 * 32 + lane]), acc2);
    float a0, a1; unpack2(acc2, a0, a1);
    float acc = __fadd_rn(__fadd_rn(a0, a1), b3s[lane]);
    out[(size_t)p * 32 + lane] = gelu_fast(acc);
}

// ---------------------------------------------------------------------------
// launch
// ---------------------------------------------------------------------------
extern "C" void kernel_launch(void* const* d_in, const int* in_sizes, int n_in,
                              void* d_out, int out_size) {
    const float* gv = (const float*)d_in[0];
    const float* gf = (const float*)d_in[1];
    const float* pv = (const float*)d_in[2];
    const float* pf = (const float*)d_in[3];
    const float* W1 = (const float*)d_in[4];
    const float* b1 = (const float*)d_in[5];
    const float* W2 = (const float*)d_in[6];
    const float* b2 = (const float*)d_in[7];
    const float* W3 = (const float*)d_in[8];
    const float* b3 = (const float*)d_in[9];
    float* out = (float*)d_out;

    gpre_kernel<<<NGRID / 32, 256>>>(gf, W1, W2, W3);
    fused_kernel<<<NPTS / 8, 256>>>(gv, pv, pf, W1, b1, b2, b3, out);
}

// round 8
// speedup vs baseline: 1.5184x; 1.5184x over previous
#include <cuda_runtime.h>
#include <math.h>
#include <stdint.h>

// ---------------------------------------------------------------------------
// GridFeatureToPointGraphConv — R8: layer-2 on warp-level tf32 mma.sync
// (m16n8k8, sm_80-class HMMA — works on the harness's compute_103 target).
// h1 written tf32-rounded into pitch-68 shared tile; W2 pre-packed into exact
// per-lane B fragments; D init = bias; butterfly mean epilogue.
// ---------------------------------------------------------------------------

#define RES 48
#define NGRID (RES*RES*RES)      // 110592
#define NPTS 65536
#define KNN 16
#define H1P 68                   // h1 tile pitch in floats (bank-conflict-free)

typedef unsigned long long u64;

__device__ float g_Gpre[NGRID * 64];    // 28.3 MB (L2-resident)
__device__ uint2 g_W2frag[8 * 4 * 32];  // per-lane tf32 B fragments [s][nt][lane]
__device__ u64   g_W3p[16 * 32];        // {W3[2i][o], W3[2i+1][o]}

// ---- f32x2 helpers -------------------------------------------------------
__device__ __forceinline__ u64 pack2(float lo, float hi) {
    u64 r; asm("mov.b64 %0, {%1,%2};" : "=l"(r) : "f"(lo), "f"(hi)); return r;
}
__device__ __forceinline__ void unpack2(u64 v, float& lo, float& hi) {
    asm("mov.b64 {%0,%1}, %2;" : "=f"(lo), "=f"(hi) : "l"(v));
}
__device__ __forceinline__ u64 fma2(u64 a, u64 b, u64 c) {
    u64 d; asm("fma.rn.f32x2 %0, %1, %2, %3;" : "=l"(d) : "l"(a), "l"(b), "l"(c)); return d;
}
__device__ __forceinline__ u64 mul2(u64 a, u64 b) {
    u64 d; asm("mul.rn.f32x2 %0, %1, %2;" : "=l"(d) : "l"(a), "l"(b)); return d;
}
__device__ __forceinline__ u64 add2(u64 a, u64 b) {
    u64 d; asm("add.rn.f32x2 %0, %1, %2;" : "=l"(d) : "l"(a), "l"(b)); return d;
}
__device__ __forceinline__ float ex2f(float x) {
    float r; asm("ex2.approx.f32 %0, %1;" : "=f"(r) : "f"(x)); return r;
}
__device__ __forceinline__ float rcpf(float x) {
    float r; asm("rcp.approx.f32 %0, %1;" : "=f"(r) : "f"(x)); return r;
}
__device__ __forceinline__ uint32_t s2u(const void* p) {
    return (uint32_t)__cvta_generic_to_shared(p);
}
__device__ __forceinline__ uint32_t tf32r(float x) {
    uint32_t r; asm("cvt.rna.tf32.f32 %0, %1;" : "=r"(r) : "f"(x)); return r;
}

// gelu_tanh(x) == x / (1 + e^{-p}), p = 1.5957691216x + 0.07135481681x^3
__device__ __forceinline__ float gelu_fast(float x) {
    float u = x * x;
    float w = __fmaf_rn(0.07135481681f, u, 1.5957691216f);
    float p = x * w;
    float e = __expf(-p);
    return __fdividef(x, 1.0f + e);
}
__device__ __forceinline__ u64 gelu2(u64 x) {
    const u64 C0 = pack2(0.07135481681f, 0.07135481681f);
    const u64 C1 = pack2(1.5957691216f, 1.5957691216f);
    const u64 NL2E = pack2(-1.442695041f, -1.442695041f);
    const u64 ONE2 = pack2(1.0f, 1.0f);
    u64 u = mul2(x, x);
    u64 w = fma2(u, C0, C1);
    u64 p = mul2(x, w);
    u64 m = mul2(p, NL2E);
    float m0, m1; unpack2(m, m0, m1);
    u64 e = pack2(ex2f(m0), ex2f(m1));
    u64 den = add2(ONE2, e);
    float d0, d1; unpack2(den, d0, d1);
    u64 r = pack2(rcpf(d0), rcpf(d1));
    return mul2(x, r);
}

// tf32 mma m16n8k8: D(16x8) += A(16x8) * B(8x8)
__device__ __forceinline__ void mma_tf32(float& d0, float& d1, float& d2, float& d3,
                                         uint32_t a0, uint32_t a1, uint32_t a2, uint32_t a3,
                                         uint32_t b0, uint32_t b1) {
    asm volatile(
        "mma.sync.aligned.m16n8k8.row.col.f32.tf32.tf32.f32 "
        "{%0,%1,%2,%3}, {%4,%5,%6,%7}, {%8,%9}, {%0,%1,%2,%3};"
        : "+f"(d0), "+f"(d1), "+f"(d2), "+f"(d3)
        : "r"(a0), "r"(a1), "r"(a2), "r"(a3), "r"(b0), "r"(b1));
}

// ---------------------------------------------------------------------------
// Kernel 1: Gpre = grid_features @ W1[0:32]  + weight packing (block 0)
// ---------------------------------------------------------------------------
__global__ __launch_bounds__(256) void gpre_kernel(const float* __restrict__ gf,
                                                   const float* __restrict__ W1,
                                                   const float* __restrict__ W2,
                                                   const float* __restrict__ W3) {
    __shared__ float W1s[32 * 64];
    __shared__ float gfs[4 * 32];
    int tid = threadIdx.x;
    for (int t = tid; t < 32 * 64; t += 256) W1s[t] = W1[t];

    if (blockIdx.x == 0) {
        // B fragments: [s][nt][lane]: b0=W2[8s+t][8nt+g], b1=W2[8s+t+4][8nt+g]
        for (int j = tid; j < 8 * 4 * 32; j += 256) {
            int s = j >> 7, nt = (j >> 5) & 3, ln = j & 31;
            int t = ln & 3, g = ln >> 2;
            uint2 v;
            v.x = tf32r(W2[(8 * s + t) * 32 + 8 * nt + g]);
            v.y = tf32r(W2[(8 * s + t + 4) * 32 + 8 * nt + g]);
            g_W2frag[j] = v;
        }
        for (int j = tid; j < 16 * 32; j += 256) {
            int i = j >> 5, o = j & 31;
            g_W3p[j] = pack2(W3[(2 * i) * 32 + o], W3[(2 * i + 1) * 32 + o]);
        }
    }

    int i = tid & 63;
    int v = tid >> 6;
    int base = blockIdx.x * 32;
    for (int it = 0; it < 8; ++it) {
        int g = base + it * 4;
        __syncthreads();
        if (tid < 128) gfs[tid] = gf[(size_t)g * 32 + tid];
        __syncthreads();
        float acc = 0.0f;
        #pragma unroll
        for (int c = 0; c < 32; ++c)
            acc = fmaf(gfs[v * 32 + c], W1s[c * 64 + i], acc);
        g_Gpre[(size_t)g * 64 + (size_t)tid] = acc;
    }
}

// ---------------------------------------------------------------------------
// Selection helpers (numerics identical to R4)
// ---------------------------------------------------------------------------
__device__ __forceinline__ float cand_dist(int t, int ix0, int iy0, int iz0,
                                           const float* __restrict__ lins,
                                           float qx, float qy, float qz, float qq) {
    int a = t >> 4, b = (t >> 2) & 3, c = t & 3;
    float px = lins[ix0 + a], py = lins[iy0 + b], pz = lins[iz0 + c];
    float pp = __fadd_rn(__fadd_rn(__fmul_rn(px, px), __fmul_rn(py, py)), __fmul_rn(pz, pz));
    float dot = __fmaf_rn(qz, pz, __fmaf_rn(qy, py, __fmul_rn(qx, px)));
    return __fadd_rn(__fsub_rn(qq, __fadd_rn(dot, dot)), pp);
}
__device__ __forceinline__ unsigned int fmap(float d) {
    unsigned int b = __float_as_uint(d);
    return (b & 0x80000000u) ? ~b : (b | 0x80000000u);
}
__device__ __forceinline__ u64 bitonic_ce(u64 key, int j, bool up, int lane) {
    u64 pk = __shfl_xor_sync(0xffffffffu, key, j);
    bool lower = ((lane & j) == 0);
    u64 mn = (key < pk) ? key : pk;
    u64 mx = (key < pk) ? pk : key;
    return ((lower == up)) ? mn : mx;
}

// ---------------------------------------------------------------------------
// Kernel 2: fused. One warp per point; layer-2 via mma.sync tf32.
// ---------------------------------------------------------------------------
__global__ __launch_bounds__(256, 2) void fused_kernel(
    const float* __restrict__ gv,
    const float* __restrict__ pv,
    const float* __restrict__ pf,
    const float* __restrict__ W1,
    const float* __restrict__ b1,
    const float* __restrict__ b2,
    const float* __restrict__ b3,
    float* __restrict__ out)
{
    __shared__ float lins[RES];
    __shared__ __align__(16) float W1s[35 * 64];       // W1 rows 32..66
    __shared__ float b1s[64];
    __shared__ float b2s[32];
    __shared__ float b3s[32];
    __shared__ __align__(16) uint32_t h1s[8][16 * H1P]; // tf32 h1, pitch 68
    __shared__ __align__(16) u64 aggs[8][16];

    int tid = threadIdx.x;
    for (int t = tid; t < 35 * 64; t += 256) W1s[t] = W1[32 * 64 + t];
    if (tid < 64) b1s[tid] = b1[tid];
    if (tid >= 64 && tid < 96)  b2s[tid - 64] = b2[tid - 64];
    if (tid >= 96 && tid < 128) b3s[tid - 96] = b3[tid - 96];
    if (tid >= 128 && tid < 128 + RES)
        lins[tid - 128] = __fmul_rn(gv[3 * (tid - 128) + 2], 24.0f);
    __syncthreads();

    const int w = tid >> 5;
    const int lane = tid & 31;
    const int p = blockIdx.x * 8 + w;
    const int t4 = lane & 3;
    const int g4 = lane >> 2;

    // point coords (scaled)
    float qxu = __ldg(&pv[p * 3 + 0]);
    float qyu = __ldg(&pv[p * 3 + 1]);
    float qzu = __ldg(&pv[p * 3 + 2]);
    float qx = __fmul_rn(qxu, 24.0f);
    float qy = __fmul_rn(qyu, 24.0f);
    float qz = __fmul_rn(qzu, 24.0f);
    float qq = __fadd_rn(__fadd_rn(__fmul_rn(qx, qx), __fmul_rn(qy, qy)), __fmul_rn(qz, qz));

    // per-point layer-1 partial (channels 2*lane, 2*lane+1)
    const u64* W1su = reinterpret_cast<const u64*>(W1s);
    u64 pre2 = pack2(b1s[lane * 2], b1s[lane * 2 + 1]);
    {
        const float4* pf4 = reinterpret_cast<const float4*>(pf + (size_t)p * 32);
        #pragma unroll
        for (int c4 = 0; c4 < 8; ++c4) {
            float4 f = __ldg(&pf4[c4]);
            pre2 = fma2(pack2(f.x, f.x), W1su[(c4 * 4 + 0) * 32 + lane], pre2);
            pre2 = fma2(pack2(f.y, f.y), W1su[(c4 * 4 + 1) * 32 + lane], pre2);
            pre2 = fma2(pack2(f.z, f.z), W1su[(c4 * 4 + 2) * 32 + lane], pre2);
            pre2 = fma2(pack2(f.w, f.w), W1su[(c4 * 4 + 3) * 32 + lane], pre2);
        }
    }
    u64 w1rx2 = W1su[32 * 32 + lane];
    u64 w1ry2 = W1su[33 * 32 + lane];
    u64 w1rz2 = W1su[34 * 32 + lane];

    // ---- Phase A: selection via bitonic sort of 64 (d, t) keys ----
    int ix0 = min(max((int)floorf((qxu + 1.0f) * 23.5f) - 1, 0), RES - 4);
    int iy0 = min(max((int)floorf((qyu + 1.0f) * 23.5f) - 1, 0), RES - 4);
    int iz0 = min(max((int)floorf((qzu + 1.0f) * 23.5f) - 1, 0), RES - 4);

    float dA = cand_dist(lane,      ix0, iy0, iz0, lins, qx, qy, qz, qq);
    float dB = cand_dist(lane + 32, ix0, iy0, iz0, lins, qx, qy, qz, qq);
    u64 key0 = ((u64)fmap(dA) << 32) | (unsigned int)lane;
    u64 key1 = ((u64)fmap(dB) << 32) | (unsigned int)(lane + 32);

    #pragma unroll
    for (int ks = 2; ks <= 32; ks <<= 1) {
        bool up0 = ((lane & ks) == 0);
        bool up1 = (((lane + 32) & ks) == 0);
        #pragma unroll
        for (int j = ks >> 1; j > 0; j >>= 1) {
            key0 = bitonic_ce(key0, j, up0, lane);
            key1 = bitonic_ce(key1, j, up1, lane);
        }
    }
    {
        key0 = (key0 < key1) ? key0 : key1;
        #pragma unroll
        for (int j = 16; j > 0; j >>= 1)
            key0 = bitonic_ce(key0, j, true, lane);
    }
    int myt = (int)((unsigned int)key0 & 63u);   // lane k (<16) holds rank-k neighbor

    // ---- Phase B1: edge layer-1, write tf32 h1 into pitch-68 tile ----
    const u64* Gpreu = reinterpret_cast<const u64*>(g_Gpre);
    const int gbase = ix0 * (RES * RES) + iy0 * RES + iz0;
    const uint32_t stsBase = s2u(&h1s[w][0]) + 8u * (uint32_t)lane;
    #pragma unroll 4
    for (int k = 0; k < KNN; ++k) {
        int t = __shfl_sync(0xffffffffu, myt, k);
        int a = t >> 4, b = (t >> 2) & 3, c = t & 3;
        int gm = gbase + a * (RES * RES) + b * RES + c;
        float rx = __fsub_rn(lins[ix0 + a], qx);
        float ry = __fsub_rn(lins[iy0 + b], qy);
        float rz = __fsub_rn(lins[iz0 + c], qz);

        u64 gp = __ldg(&Gpreu[(size_t)gm * 32 + lane]);
        u64 t2 = add2(pre2, gp);
        t2 = fma2(pack2(rx, rx), w1rx2, t2);
        t2 = fma2(pack2(ry, ry), w1ry2, t2);
        t2 = fma2(pack2(rz, rz), w1rz2, t2);
        u64 h = gelu2(t2);
        float h0, h1f; unpack2(h, h0, h1f);
        uint32_t r0 = tf32r(h0), r1 = tf32r(h1f);
        asm volatile("st.shared.v2.b32 [%0], {%1,%2};"
                     :: "r"(stsBase + (uint32_t)(k * H1P * 4)), "r"(r0), "r"(r1));
    }
    __syncwarp();

    // ---- B fragments (W2 tf32, per-lane layout) ----
    uint2 bf[8][4];
    #pragma unroll
    for (int s = 0; s < 8; ++s)
        #pragma unroll
        for (int nt = 0; nt < 4; ++nt)
            bf[s][nt] = __ldg(&g_W2frag[(s * 4 + nt) * 32 + lane]);

    // ---- Phase B2: D(16x32) = h1(16x64) @ W2(64x32), bias-initialized ----
    float d0[4], d1[4], d2[4], d3[4];
    #pragma unroll
    for (int nt = 0; nt < 4; ++nt) {
        float bA = b2s[8 * nt + 2 * t4];
        float bB = b2s[8 * nt + 2 * t4 + 1];
        d0[nt] = bA; d1[nt] = bB; d2[nt] = bA; d3[nt] = bB;
    }
    {
        const uint32_t* h1u = &h1s[w][0];
        const int fb = g4 * H1P + t4;
        #pragma unroll
        for (int s = 0; s < 8; ++s) {
            uint32_t a0 = h1u[fb + 8 * s];
            uint32_t a1 = h1u[fb + 8 * H1P + 8 * s];
            uint32_t a2 = h1u[fb + 4 + 8 * s];
            uint32_t a3 = h1u[fb + 8 * H1P + 4 + 8 * s];
            #pragma unroll
            for (int nt = 0; nt < 4; ++nt)
                mma_tf32(d0[nt], d1[nt], d2[nt], d3[nt],
                         a0, a1, a2, a3, bf[s][nt].x, bf[s][nt].y);
        }
    }

    // ---- epilogue: gelu, mean over 16 edges, write agg pairs ----
    const u64 HK2 = pack2(0.0625f, 0.0625f);
    #pragma unroll
    for (int nt = 0; nt < 4; ++nt) {
        u64 v = add2(gelu2(pack2(d0[nt], d1[nt])), gelu2(pack2(d2[nt], d3[nt])));
        v = add2(v, __shfl_xor_sync(0xffffffffu, v, 4));
        v = add2(v, __shfl_xor_sync(0xffffffffu, v, 8));
        v = add2(v, __shfl_xor_sync(0xffffffffu, v, 16));
        if (lane < 4) aggs[w][nt * 4 + lane] = mul2(v, HK2);
    }
    __syncwarp();

    // ---- out transform (packed) ----
    {
        const u64* ag = aggs[w];
        u64 acc2 = pack2(0.0f, 0.0f);
        #pragma unroll
        for (int i2 = 0; i2 < 16; ++i2)
            acc2 = fma2(ag[i2], __ldg(&g_W3p[i2 * 32 + lane]), acc2);
        float a0, a1; unpack2(acc2, a0, a1);
        float acc = __fadd_rn(__fadd_rn(a0, a1), b3s[lane]);
        out[(size_t)p * 32 + lane] = gelu_fast(acc);
    }
}

// ---------------------------------------------------------------------------
// launch
// ---------------------------------------------------------------------------
extern "C" void kernel_launch(void* const* d_in, const int* in_sizes, int n_in,
                              void* d_out, int out_size) {
    const float* gv = (const float*)d_in[0];
    const float* gf = (const float*)d_in[1];
    const float* pv = (const float*)d_in[2];
    const float* pf = (const float*)d_in[3];
    const float* W1 = (const float*)d_in[4];
    const float* b1 = (const float*)d_in[5];
    const float* W2 = (const float*)d_in[6];
    const float* b2 = (const float*)d_in[7];
    const float* W3 = (const float*)d_in[8];
    const float* b3 = (const float*)d_in[9];
    float* out = (float*)d_out;

    gpre_kernel<<<NGRID / 32, 256>>>(gf, W1, W2, W3);
    fused_kernel<<<NPTS / 8, 256>>>(gv, pv, pf, W1, b1, b2, b3, out);
}

// round 9
// speedup vs baseline: 1.7442x; 1.1487x over previous
#include <cuda_runtime.h>
#include <math.h>
#include <stdint.h>

// ---------------------------------------------------------------------------
// GridFeatureToPointGraphConv — R9: occupancy push. W2 mma fragments moved to
// shared (freeing ~64 regs), h1 tile XOR-swizzled at pitch 64, W1 rows in
// L1-cached global pairs; 3 blocks/SM. Math identical to R8.
// ---------------------------------------------------------------------------

#define RES 48
#define NGRID (RES*RES*RES)      // 110592
#define NPTS 65536
#define KNN 16

typedef unsigned long long u64;

__device__ float g_Gpre[NGRID * 64];    // 28.3 MB (L2-resident)
__device__ uint2 g_W2frag[8 * 4 * 32];  // per-lane tf32 B fragments [s][nt][lane]
__device__ u64   g_W1sp[32 * 32];       // W1 self rows 32..63, channel pairs
__device__ u64   g_W1rp[3 * 32];        // W1 rel rows 64..66, channel pairs
__device__ u64   g_W3p[16 * 32];        // {W3[2i][o], W3[2i+1][o]}

// ---- f32x2 helpers -------------------------------------------------------
__device__ __forceinline__ u64 pack2(float lo, float hi) {
    u64 r; asm("mov.b64 %0, {%1,%2};" : "=l"(r) : "f"(lo), "f"(hi)); return r;
}
__device__ __forceinline__ void unpack2(u64 v, float& lo, float& hi) {
    asm("mov.b64 {%0,%1}, %2;" : "=f"(lo), "=f"(hi) : "l"(v));
}
__device__ __forceinline__ u64 fma2(u64 a, u64 b, u64 c) {
    u64 d; asm("fma.rn.f32x2 %0, %1, %2, %3;" : "=l"(d) : "l"(a), "l"(b), "l"(c)); return d;
}
__device__ __forceinline__ u64 mul2(u64 a, u64 b) {
    u64 d; asm("mul.rn.f32x2 %0, %1, %2;" : "=l"(d) : "l"(a), "l"(b)); return d;
}
__device__ __forceinline__ u64 add2(u64 a, u64 b) {
    u64 d; asm("add.rn.f32x2 %0, %1, %2;" : "=l"(d) : "l"(a), "l"(b)); return d;
}
__device__ __forceinline__ float ex2f(float x) {
    float r; asm("ex2.approx.f32 %0, %1;" : "=f"(r) : "f"(x)); return r;
}
__device__ __forceinline__ float rcpf(float x) {
    float r; asm("rcp.approx.f32 %0, %1;" : "=f"(r) : "f"(x)); return r;
}
__device__ __forceinline__ uint32_t s2u(const void* p) {
    return (uint32_t)__cvta_generic_to_shared(p);
}
__device__ __forceinline__ uint32_t tf32r(float x) {
    uint32_t r; asm("cvt.rna.tf32.f32 %0, %1;" : "=r"(r) : "f"(x)); return r;
}

// gelu_tanh(x) == x / (1 + e^{-p}), p = 1.5957691216x + 0.07135481681x^3
__device__ __forceinline__ float gelu_fast(float x) {
    float u = x * x;
    float w = __fmaf_rn(0.07135481681f, u, 1.5957691216f);
    float p = x * w;
    float e = __expf(-p);
    return __fdividef(x, 1.0f + e);
}
__device__ __forceinline__ u64 gelu2(u64 x) {
    const u64 C0 = pack2(0.07135481681f, 0.07135481681f);
    const u64 C1 = pack2(1.5957691216f, 1.5957691216f);
    const u64 NL2E = pack2(-1.442695041f, -1.442695041f);
    const u64 ONE2 = pack2(1.0f, 1.0f);
    u64 u = mul2(x, x);
    u64 w = fma2(u, C0, C1);
    u64 p = mul2(x, w);
    u64 m = mul2(p, NL2E);
    float m0, m1; unpack2(m, m0, m1);
    u64 e = pack2(ex2f(m0), ex2f(m1));
    u64 den = add2(ONE2, e);
    float d0, d1; unpack2(den, d0, d1);
    u64 r = pack2(rcpf(d0), rcpf(d1));
    return mul2(x, r);
}

// tf32 mma m16n8k8: D(16x8) += A(16x8) * B(8x8)
__device__ __forceinline__ void mma_tf32(float& d0, float& d1, float& d2, float& d3,
                                         uint32_t a0, uint32_t a1, uint32_t a2, uint32_t a3,
                                         uint32_t b0, uint32_t b1) {
    asm volatile(
        "mma.sync.aligned.m16n8k8.row.col.f32.tf32.tf32.f32 "
        "{%0,%1,%2,%3}, {%4,%5,%6,%7}, {%8,%9}, {%0,%1,%2,%3};"
        : "+f"(d0), "+f"(d1), "+f"(d2), "+f"(d3)
        : "r"(a0), "r"(a1), "r"(a2), "r"(a3), "r"(b0), "r"(b1));
}

// ---------------------------------------------------------------------------
// Kernel 1: Gpre = grid_features @ W1[0:32]  + weight packing (block 0)
// ---------------------------------------------------------------------------
__global__ __launch_bounds__(256) void gpre_kernel(const float* __restrict__ gf,
                                                   const float* __restrict__ W1,
                                                   const float* __restrict__ W2,
                                                   const float* __restrict__ W3) {
    __shared__ float W1s[32 * 64];
    __shared__ float gfs[4 * 32];
    int tid = threadIdx.x;
    for (int t = tid; t < 32 * 64; t += 256) W1s[t] = W1[t];

    if (blockIdx.x == 0) {
        // B fragments: [s][nt][lane]: b0=W2[8s+t][8nt+g], b1=W2[8s+t+4][8nt+g]
        for (int j = tid; j < 8 * 4 * 32; j += 256) {
            int s = j >> 7, nt = (j >> 5) & 3, ln = j & 31;
            int t = ln & 3, g = ln >> 2;
            uint2 v;
            v.x = tf32r(W2[(8 * s + t) * 32 + 8 * nt + g]);
            v.y = tf32r(W2[(8 * s + t + 4) * 32 + 8 * nt + g]);
            g_W2frag[j] = v;
        }
        for (int j = tid; j < 32 * 32; j += 256) {      // W1 self rows
            int c = j >> 5, o = j & 31;
            g_W1sp[j] = pack2(W1[(32 + c) * 64 + 2 * o], W1[(32 + c) * 64 + 2 * o + 1]);
        }
        for (int j = tid; j < 3 * 32; j += 256) {       // W1 rel rows
            int r = j >> 5, o = j & 31;
            g_W1rp[j] = pack2(W1[(64 + r) * 64 + 2 * o], W1[(64 + r) * 64 + 2 * o + 1]);
        }
        for (int j = tid; j < 16 * 32; j += 256) {      // W3 pairs
            int i = j >> 5, o = j & 31;
            g_W3p[j] = pack2(W3[(2 * i) * 32 + o], W3[(2 * i + 1) * 32 + o]);
        }
    }

    int i = tid & 63;
    int v = tid >> 6;
    int base = blockIdx.x * 32;
    for (int it = 0; it < 8; ++it) {
        int g = base + it * 4;
        __syncthreads();
        if (tid < 128) gfs[tid] = gf[(size_t)g * 32 + tid];
        __syncthreads();
        float acc = 0.0f;
        #pragma unroll
        for (int c = 0; c < 32; ++c)
            acc = fmaf(gfs[v * 32 + c], W1s[c * 64 + i], acc);
        g_Gpre[(size_t)g * 64 + (size_t)tid] = acc;
    }
}

// ---------------------------------------------------------------------------
// Selection helpers (numerics identical to R4)
// ---------------------------------------------------------------------------
__device__ __forceinline__ float cand_dist(int t, int ix0, int iy0, int iz0,
                                           const float* __restrict__ lins,
                                           float qx, float qy, float qz, float qq) {
    int a = t >> 4, b = (t >> 2) & 3, c = t & 3;
    float px = lins[ix0 + a], py = lins[iy0 + b], pz = lins[iz0 + c];
    float pp = __fadd_rn(__fadd_rn(__fmul_rn(px, px), __fmul_rn(py, py)), __fmul_rn(pz, pz));
    float dot = __fmaf_rn(qz, pz, __fmaf_rn(qy, py, __fmul_rn(qx, px)));
    return __fadd_rn(__fsub_rn(qq, __fadd_rn(dot, dot)), pp);
}
__device__ __forceinline__ unsigned int fmap(float d) {
    unsigned int b = __float_as_uint(d);
    return (b & 0x80000000u) ? ~b : (b | 0x80000000u);
}
__device__ __forceinline__ u64 bitonic_ce(u64 key, int j, bool up, int lane) {
    u64 pk = __shfl_xor_sync(0xffffffffu, key, j);
    bool lower = ((lane & j) == 0);
    u64 mn = (key < pk) ? key : pk;
    u64 mx = (key < pk) ? pk : key;
    return ((lower == up)) ? mn : mx;
}

// ---------------------------------------------------------------------------
// Kernel 2: fused. One warp per point; layer-2 via mma.sync tf32.
// ---------------------------------------------------------------------------
__global__ __launch_bounds__(256, 3) void fused_kernel(
    const float* __restrict__ gv,
    const float* __restrict__ pv,
    const float* __restrict__ pf,
    const float* __restrict__ b1,
    const float* __restrict__ b2,
    const float* __restrict__ b3,
    float* __restrict__ out)
{
    __shared__ float lins[RES];
    __shared__ float b1s[64];
    __shared__ float b2s[32];
    __shared__ float b3s[32];
    __shared__ __align__(16) uint2 frs[8 * 4 * 32];       // W2 fragments (8 KB)
    __shared__ __align__(16) uint32_t h1s[8][16 * 64];    // tf32 h1, XOR-swizzled
    __shared__ __align__(16) u64 aggs[8][16];

    int tid = threadIdx.x;
    // W2 fragment tile (same for every warp)
    for (int j = tid; j < 8 * 4 * 32; j += 256) frs[j] = __ldg(&g_W2frag[j]);
    if (tid < 64) b1s[tid] = b1[tid];
    if (tid >= 64 && tid < 96)  b2s[tid - 64] = b2[tid - 64];
    if (tid >= 96 && tid < 128) b3s[tid - 96] = b3[tid - 96];
    if (tid >= 128 && tid < 128 + RES)
        lins[tid - 128] = __fmul_rn(gv[3 * (tid - 128) + 2], 24.0f);
    __syncthreads();

    const int w = tid >> 5;
    const int lane = tid & 31;
    const int p = blockIdx.x * 8 + w;
    const int t4 = lane & 3;
    const int g4 = lane >> 2;

    // point coords (scaled)
    float qxu = __ldg(&pv[p * 3 + 0]);
    float qyu = __ldg(&pv[p * 3 + 1]);
    float qzu = __ldg(&pv[p * 3 + 2]);
    float qx = __fmul_rn(qxu, 24.0f);
    float qy = __fmul_rn(qyu, 24.0f);
    float qz = __fmul_rn(qzu, 24.0f);
    float qq = __fadd_rn(__fadd_rn(__fmul_rn(qx, qx), __fmul_rn(qy, qy)), __fmul_rn(qz, qz));

    // per-point layer-1 partial (channels 2*lane, 2*lane+1)
    u64 pre2 = pack2(b1s[lane * 2], b1s[lane * 2 + 1]);
    {
        const float4* pf4 = reinterpret_cast<const float4*>(pf + (size_t)p * 32);
        #pragma unroll
        for (int c4 = 0; c4 < 8; ++c4) {
            float4 f = __ldg(&pf4[c4]);
            pre2 = fma2(pack2(f.x, f.x), __ldg(&g_W1sp[(c4 * 4 + 0) * 32 + lane]), pre2);
            pre2 = fma2(pack2(f.y, f.y), __ldg(&g_W1sp[(c4 * 4 + 1) * 32 + lane]), pre2);
            pre2 = fma2(pack2(f.z, f.z), __ldg(&g_W1sp[(c4 * 4 + 2) * 32 + lane]), pre2);
            pre2 = fma2(pack2(f.w, f.w), __ldg(&g_W1sp[(c4 * 4 + 3) * 32 + lane]), pre2);
        }
    }
    u64 w1rx2 = __ldg(&g_W1rp[0 * 32 + lane]);
    u64 w1ry2 = __ldg(&g_W1rp[1 * 32 + lane]);
    u64 w1rz2 = __ldg(&g_W1rp[2 * 32 + lane]);

    // ---- Phase A: selection via bitonic sort of 64 (d, t) keys ----
    int ix0 = min(max((int)floorf((qxu + 1.0f) * 23.5f) - 1, 0), RES - 4);
    int iy0 = min(max((int)floorf((qyu + 1.0f) * 23.5f) - 1, 0), RES - 4);
    int iz0 = min(max((int)floorf((qzu + 1.0f) * 23.5f) - 1, 0), RES - 4);

    float dA = cand_dist(lane,      ix0, iy0, iz0, lins, qx, qy, qz, qq);
    float dB = cand_dist(lane + 32, ix0, iy0, iz0, lins, qx, qy, qz, qq);
    u64 key0 = ((u64)fmap(dA) << 32) | (unsigned int)lane;
    u64 key1 = ((u64)fmap(dB) << 32) | (unsigned int)(lane + 32);

    #pragma unroll
    for (int ks = 2; ks <= 32; ks <<= 1) {
        bool up0 = ((lane & ks) == 0);
        bool up1 = (((lane + 32) & ks) == 0);
        #pragma unroll
        for (int j = ks >> 1; j > 0; j >>= 1) {
            key0 = bitonic_ce(key0, j, up0, lane);
            key1 = bitonic_ce(key1, j, up1, lane);
        }
    }
    {
        key0 = (key0 < key1) ? key0 : key1;
        #pragma unroll
        for (int j = 16; j > 0; j >>= 1)
            key0 = bitonic_ce(key0, j, true, lane);
    }
    int myt = (int)((unsigned int)key0 & 63u);   // lane k (<16) holds rank-k neighbor

    // ---- Phase B1: edge layer-1, write tf32 h1 into swizzled tile ----
    // word(row, col) = row*64 + (col ^ (4*row & 31))
    const u64* Gpreu = reinterpret_cast<const u64*>(g_Gpre);
    const int gbase = ix0 * (RES * RES) + iy0 * RES + iz0;
    const uint32_t h1base = s2u(&h1s[w][0]);
    #pragma unroll 4
    for (int k = 0; k < KNN; ++k) {
        int t = __shfl_sync(0xffffffffu, myt, k);
        int a = t >> 4, b = (t >> 2) & 3, c = t & 3;
        int gm = gbase + a * (RES * RES) + b * RES + c;
        float rx = __fsub_rn(lins[ix0 + a], qx);
        float ry = __fsub_rn(lins[iy0 + b], qy);
        float rz = __fsub_rn(lins[iz0 + c], qz);

        u64 gp = __ldg(&Gpreu[(size_t)gm * 32 + lane]);
        u64 t2 = add2(pre2, gp);
        t2 = fma2(pack2(rx, rx), w1rx2, t2);
        t2 = fma2(pack2(ry, ry), w1ry2, t2);
        t2 = fma2(pack2(rz, rz), w1rz2, t2);
        u64 h = gelu2(t2);
        float h0, h1f; unpack2(h, h0, h1f);
        uint32_t r0 = tf32r(h0), r1 = tf32r(h1f);
        uint32_t word = (uint32_t)(k * 64) + (((uint32_t)(2 * lane)) ^ (uint32_t)((4 * k) & 31));
        asm volatile("st.shared.v2.b32 [%0], {%1,%2};"
                     :: "r"(h1base + word * 4u), "r"(r0), "r"(r1));
    }
    __syncwarp();

    // ---- Phase B2: D(16x32) = h1(16x64) @ W2(64x32), bias-initialized ----
    float d0[4], d1[4], d2[4], d3[4];
    #pragma unroll
    for (int nt = 0; nt < 4; ++nt) {
        float bA = b2s[8 * nt + 2 * t4];
        float bB = b2s[8 * nt + 2 * t4 + 1];
        d0[nt] = bA; d1[nt] = bB; d2[nt] = bA; d3[nt] = bB;
    }
    {
        const uint32_t* h1u = &h1s[w][0];
        const int xr = 4 * g4;             // (4*g4)&31, g4<8
        #pragma unroll 2
        for (int s = 0; s < 8; ++s) {
            int c0 = 8 * s + t4;
            uint32_t a0 = h1u[g4 * 64 + (c0 ^ xr)];
            uint32_t a1 = h1u[(g4 + 8) * 64 + (c0 ^ xr)];
            uint32_t a2 = h1u[g4 * 64 + ((c0 + 4) ^ xr)];
            uint32_t a3 = h1u[(g4 + 8) * 64 + ((c0 + 4) ^ xr)];
            #pragma unroll
            for (int nt = 0; nt < 4; ++nt) {
                uint2 bf = frs[(s * 4 + nt) * 32 + lane];
                mma_tf32(d0[nt], d1[nt], d2[nt], d3[nt],
                         a0, a1, a2, a3, bf.x, bf.y);
            }
        }
    }

    // ---- epilogue: gelu, mean over 16 edges, write agg pairs ----
    const u64 HK2 = pack2(0.0625f, 0.0625f);
    #pragma unroll
    for (int nt = 0; nt < 4; ++nt) {
        u64 v = add2(gelu2(pack2(d0[nt], d1[nt])), gelu2(pack2(d2[nt], d3[nt])));
        v = add2(v, __shfl_xor_sync(0xffffffffu, v, 4));
        v = add2(v, __shfl_xor_sync(0xffffffffu, v, 8));
        v = add2(v, __shfl_xor_sync(0xffffffffu, v, 16));
        if (lane < 4) aggs[w][nt * 4 + lane] = mul2(v, HK2);
    }
    __syncwarp();

    // ---- out transform (packed) ----
    {
        const u64* ag = aggs[w];
        u64 acc2 = pack2(0.0f, 0.0f);
        #pragma unroll
        for (int i2 = 0; i2 < 16; ++i2)
            acc2 = fma2(ag[i2], __ldg(&g_W3p[i2 * 32 + lane]), acc2);
        float a0, a1; unpack2(acc2, a0, a1);
        float acc = __fadd_rn(__fadd_rn(a0, a1), b3s[lane]);
        out[(size_t)p * 32 + lane] = gelu_fast(acc);
    }
}

// ---------------------------------------------------------------------------
// launch
// ---------------------------------------------------------------------------
extern "C" void kernel_launch(void* const* d_in, const int* in_sizes, int n_in,
                              void* d_out, int out_size) {
    const float* gv = (const float*)d_in[0];
    const float* gf = (const float*)d_in[1];
    const float* pv = (const float*)d_in[2];
    const float* pf = (const float*)d_in[3];
    const float* W1 = (const float*)d_in[4];
    const float* b1 = (const float*)d_in[5];
    const float* W2 = (const float*)d_in[6];
    const float* b2 = (const float*)d_in[7];
    const float* W3 = (const float*)d_in[8];
    const float* b3 = (const float*)d_in[9];
    float* out = (float*)d_out;

    gpre_kernel<<<NGRID / 32, 256>>>(gf, W1, W2, W3);
    fused_kernel<<<NPTS / 8, 256>>>(gv, pv, pf, b1, b2, b3, out);
}

// round 10
// speedup vs baseline: 1.7854x; 1.0237x over previous
#include <cuda_runtime.h>
#include <math.h>
#include <stdint.h>

// ---------------------------------------------------------------------------
// GridFeatureToPointGraphConv — R10: 4 blocks/SM (64-reg cap), B1 rel/gm
// precomputed to smem (kills per-k decode ALU), W2 frag tile as [s][lane][nt]
// (LDS.128), rewritten double-buffered gpre kernel. Numerics identical to R9.
// ---------------------------------------------------------------------------

#define RES 48
#define NGRID (RES*RES*RES)      // 110592
#define NPTS 65536
#define KNN 16

typedef unsigned long long u64;

__device__ float g_Gpre[NGRID * 64];    // 28.3 MB (L2-resident)
__device__ uint2 g_W2frag[8 * 32 * 4];  // per-lane tf32 B fragments [s][lane][nt]
__device__ u64   g_W1sp[32 * 32];       // W1 self rows 32..63, channel pairs
__device__ u64   g_W1rp[3 * 32];        // W1 rel rows 64..66, channel pairs
__device__ u64   g_W3p[16 * 32];        // {W3[2i][o], W3[2i+1][o]}

// ---- f32x2 helpers -------------------------------------------------------
__device__ __forceinline__ u64 pack2(float lo, float hi) {
    u64 r; asm("mov.b64 %0, {%1,%2};" : "=l"(r) : "f"(lo), "f"(hi)); return r;
}
__device__ __forceinline__ void unpack2(u64 v, float& lo, float& hi) {
    asm("mov.b64 {%0,%1}, %2;" : "=f"(lo), "=f"(hi) : "l"(v));
}
__device__ __forceinline__ u64 fma2(u64 a, u64 b, u64 c) {
    u64 d; asm("fma.rn.f32x2 %0, %1, %2, %3;" : "=l"(d) : "l"(a), "l"(b), "l"(c)); return d;
}
__device__ __forceinline__ u64 mul2(u64 a, u64 b) {
    u64 d; asm("mul.rn.f32x2 %0, %1, %2;" : "=l"(d) : "l"(a), "l"(b)); return d;
}
__device__ __forceinline__ u64 add2(u64 a, u64 b) {
    u64 d; asm("add.rn.f32x2 %0, %1, %2;" : "=l"(d) : "l"(a), "l"(b)); return d;
}
__device__ __forceinline__ float ex2f(float x) {
    float r; asm("ex2.approx.f32 %0, %1;" : "=f"(r) : "f"(x)); return r;
}
__device__ __forceinline__ float rcpf(float x) {
    float r; asm("rcp.approx.f32 %0, %1;" : "=f"(r) : "f"(x)); return r;
}
__device__ __forceinline__ uint32_t s2u(const void* p) {
    return (uint32_t)__cvta_generic_to_shared(p);
}
__device__ __forceinline__ uint32_t tf32r(float x) {
    uint32_t r; asm("cvt.rna.tf32.f32 %0, %1;" : "=r"(r) : "f"(x)); return r;
}

// gelu_tanh(x) == x / (1 + e^{-p}), p = 1.5957691216x + 0.07135481681x^3
__device__ __forceinline__ float gelu_fast(float x) {
    float u = x * x;
    float w = __fmaf_rn(0.07135481681f, u, 1.5957691216f);
    float p = x * w;
    float e = __expf(-p);
    return __fdividef(x, 1.0f + e);
}
__device__ __forceinline__ u64 gelu2(u64 x) {
    const u64 C0 = pack2(0.07135481681f, 0.07135481681f);
    const u64 C1 = pack2(1.5957691216f, 1.5957691216f);
    const u64 NL2E = pack2(-1.442695041f, -1.442695041f);
    const u64 ONE2 = pack2(1.0f, 1.0f);
    u64 u = mul2(x, x);
    u64 w = fma2(u, C0, C1);
    u64 p = mul2(x, w);
    u64 m = mul2(p, NL2E);
    float m0, m1; unpack2(m, m0, m1);
    u64 e = pack2(ex2f(m0), ex2f(m1));
    u64 den = add2(ONE2, e);
    float d0, d1; unpack2(den, d0, d1);
    u64 r = pack2(rcpf(d0), rcpf(d1));
    return mul2(x, r);
}

// tf32 mma m16n8k8
__device__ __forceinline__ void mma_tf32(float& d0, float& d1, float& d2, float& d3,
                                         uint32_t a0, uint32_t a1, uint32_t a2, uint32_t a3,
                                         uint32_t b0, uint32_t b1) {
    asm volatile(
        "mma.sync.aligned.m16n8k8.row.col.f32.tf32.tf32.f32 "
        "{%0,%1,%2,%3}, {%4,%5,%6,%7}, {%8,%9}, {%0,%1,%2,%3};"
        : "+f"(d0), "+f"(d1), "+f"(d2), "+f"(d3)
        : "r"(a0), "r"(a1), "r"(a2), "r"(a3), "r"(b0), "r"(b1));
}

// ---------------------------------------------------------------------------
// Kernel 1: Gpre (double-buffered, 1 channel-pair per thread) + weight packing
// ---------------------------------------------------------------------------
__global__ __launch_bounds__(256) void gpre_kernel(const float* __restrict__ gf,
                                                   const float* __restrict__ W1,
                                                   const float* __restrict__ W2,
                                                   const float* __restrict__ W3) {
    __shared__ u64 W1p[32 * 32];          // W1 rows 0..31, channel pairs
    __shared__ float gfs[2][8 * 32];
    int tid = threadIdx.x;
    for (int j = tid; j < 32 * 32; j += 256) {
        int c = j >> 5, o = j & 31;
        W1p[j] = pack2(W1[c * 64 + 2 * o], W1[c * 64 + 2 * o + 1]);
    }

    if (blockIdx.x == 0) {
        // B fragments [s][lane][nt]: b0=W2[8s+t][8nt+g], b1=W2[8s+t+4][8nt+g]
        for (int j = tid; j < 8 * 32 * 4; j += 256) {
            int s = j >> 7, ln = (j >> 2) & 31, nt = j & 3;
            int t = ln & 3, g = ln >> 2;
            uint2 v;
            v.x = tf32r(W2[(8 * s + t) * 32 + 8 * nt + g]);
            v.y = tf32r(W2[(8 * s + t + 4) * 32 + 8 * nt + g]);
            g_W2frag[j] = v;
        }
        for (int j = tid; j < 32 * 32; j += 256) {
            int c = j >> 5, o = j & 31;
            g_W1sp[j] = pack2(W1[(32 + c) * 64 + 2 * o], W1[(32 + c) * 64 + 2 * o + 1]);
        }
        for (int j = tid; j < 3 * 32; j += 256) {
            int r = j >> 5, o = j & 31;
            g_W1rp[j] = pack2(W1[(64 + r) * 64 + 2 * o], W1[(64 + r) * 64 + 2 * o + 1]);
        }
        for (int j = tid; j < 16 * 32; j += 256) {
            int i = j >> 5, o = j & 31;
            g_W3p[j] = pack2(W3[(2 * i) * 32 + o], W3[(2 * i + 1) * 32 + o]);
        }
    }

    const int base = blockIdx.x * 32;
    const int v = tid >> 5;        // vertex within group of 8
    const int o = tid & 31;        // channel pair
    gfs[0][tid] = gf[(size_t)base * 32 + tid];
    __syncthreads();

    u64* Gpreu = reinterpret_cast<u64*>(g_Gpre);
    #pragma unroll
    for (int pass = 0; pass < 4; ++pass) {
        if (pass < 3)
            gfs[(pass + 1) & 1][tid] = gf[(size_t)(base + (pass + 1) * 8) * 32 + tid];
        const float* g8 = &gfs[pass & 1][v * 32];
        u64 acc = pack2(0.0f, 0.0f);
        #pragma unroll
        for (int c = 0; c < 32; ++c)
            acc = fma2(pack2(g8[c], g8[c]), W1p[c * 32 + o], acc);
        Gpreu[(size_t)(base + pass * 8 + v) * 32 + o] = acc;
        __syncthreads();
    }
}

// ---------------------------------------------------------------------------
// Selection helpers (numerics identical)
// ---------------------------------------------------------------------------
__device__ __forceinline__ float cand_dist(int t, int ix0, int iy0, int iz0,
                                           const float* __restrict__ lins,
                                           float qx, float qy, float qz, float qq) {
    int a = t >> 4, b = (t >> 2) & 3, c = t & 3;
    float px = lins[ix0 + a], py = lins[iy0 + b], pz = lins[iz0 + c];
    float pp = __fadd_rn(__fadd_rn(__fmul_rn(px, px), __fmul_rn(py, py)), __fmul_rn(pz, pz));
    float dot = __fmaf_rn(qz, pz, __fmaf_rn(qy, py, __fmul_rn(qx, px)));
    return __fadd_rn(__fsub_rn(qq, __fadd_rn(dot, dot)), pp);
}
__device__ __forceinline__ unsigned int fmap(float d) {
    unsigned int b = __float_as_uint(d);
    return (b & 0x80000000u) ? ~b : (b | 0x80000000u);
}
__device__ __forceinline__ u64 bitonic_ce(u64 key, int j, bool up, int lane) {
    u64 pk = __shfl_xor_sync(0xffffffffu, key, j);
    bool lower = ((lane & j) == 0);
    u64 mn = (key < pk) ? key : pk;
    u64 mx = (key < pk) ? pk : key;
    return ((lower == up)) ? mn : mx;
}

// ---------------------------------------------------------------------------
// Kernel 2: fused. One warp per point; layer-2 via mma.sync tf32.
// ---------------------------------------------------------------------------
__global__ __launch_bounds__(256, 4) void fused_kernel(
    const float* __restrict__ gv,
    const float* __restrict__ pv,
    const float* __restrict__ pf,
    const float* __restrict__ b1,
    const float* __restrict__ b2,
    const float* __restrict__ b3,
    float* __restrict__ out)
{
    __shared__ float lins[RES];
    __shared__ float b1s[64];
    __shared__ float b2s[32];
    __shared__ float b3s[32];
    __shared__ __align__(16) uint2 frs[8 * 32 * 4];       // W2 fragments (8 KB)
    __shared__ __align__(16) uint32_t h1s[8][16 * 64];    // tf32 h1, XOR-swizzled
    __shared__ __align__(16) u64 aggs[8][16];
    __shared__ __align__(16) u64 relx[8][16], rely[8][16], relz[8][16];
    __shared__ int gms[8][16];

    int tid = threadIdx.x;
    for (int j = tid; j < 8 * 32 * 4; j += 256) frs[j] = __ldg(&g_W2frag[j]);
    if (tid < 64) b1s[tid] = b1[tid];
    if (tid >= 64 && tid < 96)  b2s[tid - 64] = b2[tid - 64];
    if (tid >= 96 && tid < 128) b3s[tid - 96] = b3[tid - 96];
    if (tid >= 128 && tid < 128 + RES)
        lins[tid - 128] = __fmul_rn(gv[3 * (tid - 128) + 2], 24.0f);
    __syncthreads();

    const int w = tid >> 5;
    const int lane = tid & 31;
    const int p = blockIdx.x * 8 + w;
    const int t4 = lane & 3;
    const int g4 = lane >> 2;

    // point coords (scaled)
    float qxu = __ldg(&pv[p * 3 + 0]);
    float qyu = __ldg(&pv[p * 3 + 1]);
    float qzu = __ldg(&pv[p * 3 + 2]);
    float qx = __fmul_rn(qxu, 24.0f);
    float qy = __fmul_rn(qyu, 24.0f);
    float qz = __fmul_rn(qzu, 24.0f);
    float qq = __fadd_rn(__fadd_rn(__fmul_rn(qx, qx), __fmul_rn(qy, qy)), __fmul_rn(qz, qz));

    // ---- Phase A: selection via bitonic sort of 64 (d, t) keys ----
    int ix0 = min(max((int)floorf((qxu + 1.0f) * 23.5f) - 1, 0), RES - 4);
    int iy0 = min(max((int)floorf((qyu + 1.0f) * 23.5f) - 1, 0), RES - 4);
    int iz0 = min(max((int)floorf((qzu + 1.0f) * 23.5f) - 1, 0), RES - 4);

    float dA = cand_dist(lane,      ix0, iy0, iz0, lins, qx, qy, qz, qq);
    float dB = cand_dist(lane + 32, ix0, iy0, iz0, lins, qx, qy, qz, qq);
    u64 key0 = ((u64)fmap(dA) << 32) | (unsigned int)lane;
    u64 key1 = ((u64)fmap(dB) << 32) | (unsigned int)(lane + 32);

    #pragma unroll
    for (int ks = 2; ks <= 32; ks <<= 1) {
        bool up0 = ((lane & ks) == 0);
        bool up1 = (((lane + 32) & ks) == 0);
        #pragma unroll
        for (int j = ks >> 1; j > 0; j >>= 1) {
            key0 = bitonic_ce(key0, j, up0, lane);
            key1 = bitonic_ce(key1, j, up1, lane);
        }
    }
    {
        key0 = (key0 < key1) ? key0 : key1;
        #pragma unroll
        for (int j = 16; j > 0; j >>= 1)
            key0 = bitonic_ce(key0, j, true, lane);
    }

    // ---- rank-k lanes stash rel/gm to smem (same FSUB on same lins) ----
    const int gbase = ix0 * (RES * RES) + iy0 * RES + iz0;
    if (lane < KNN) {
        int t = (int)((unsigned int)key0 & 63u);
        int a = t >> 4, b = (t >> 2) & 3, c = t & 3;
        gms[w][lane] = gbase + a * (RES * RES) + b * RES + c;
        float rx = __fsub_rn(lins[ix0 + a], qx);
        float ry = __fsub_rn(lins[iy0 + b], qy);
        float rz = __fsub_rn(lins[iz0 + c], qz);
        relx[w][lane] = pack2(rx, rx);
        rely[w][lane] = pack2(ry, ry);
        relz[w][lane] = pack2(rz, rz);
    }
    __syncwarp();

    // ---- per-point layer-1 partial (channels 2*lane, 2*lane+1) ----
    u64 pre2 = pack2(b1s[lane * 2], b1s[lane * 2 + 1]);
    {
        const float4* pf4 = reinterpret_cast<const float4*>(pf + (size_t)p * 32);
        #pragma unroll
        for (int c4 = 0; c4 < 8; ++c4) {
            float4 f = __ldg(&pf4[c4]);
            pre2 = fma2(pack2(f.x, f.x), __ldg(&g_W1sp[(c4 * 4 + 0) * 32 + lane]), pre2);
            pre2 = fma2(pack2(f.y, f.y), __ldg(&g_W1sp[(c4 * 4 + 1) * 32 + lane]), pre2);
            pre2 = fma2(pack2(f.z, f.z), __ldg(&g_W1sp[(c4 * 4 + 2) * 32 + lane]), pre2);
            pre2 = fma2(pack2(f.w, f.w), __ldg(&g_W1sp[(c4 * 4 + 3) * 32 + lane]), pre2);
        }
    }
    u64 w1rx2 = __ldg(&g_W1rp[0 * 32 + lane]);
    u64 w1ry2 = __ldg(&g_W1rp[1 * 32 + lane]);
    u64 w1rz2 = __ldg(&g_W1rp[2 * 32 + lane]);

    // ---- Phase B1: edge layer-1, write tf32 h1 into swizzled tile ----
    const u64* Gpreu = reinterpret_cast<const u64*>(g_Gpre);
    const uint32_t h1base = s2u(&h1s[w][0]);
    #pragma unroll 4
    for (int k = 0; k < KNN; ++k) {
        int gm = gms[w][k];
        u64 gp = __ldg(&Gpreu[(size_t)gm * 32 + lane]);
        u64 t2 = add2(pre2, gp);
        t2 = fma2(relx[w][k], w1rx2, t2);
        t2 = fma2(rely[w][k], w1ry2, t2);
        t2 = fma2(relz[w][k], w1rz2, t2);
        u64 h = gelu2(t2);
        float h0, h1f; unpack2(h, h0, h1f);
        uint32_t r0 = tf32r(h0), r1 = tf32r(h1f);
        uint32_t word = (uint32_t)(k * 64) + (((uint32_t)(2 * lane)) ^ (uint32_t)((4 * k) & 31));
        asm volatile("st.shared.v2.b32 [%0], {%1,%2};"
                     :: "r"(h1base + word * 4u), "r"(r0), "r"(r1));
    }
    __syncwarp();

    // ---- Phase B2: D(16x32) = h1(16x64) @ W2(64x32), bias-initialized ----
    float d0[4], d1[4], d2[4], d3[4];
    #pragma unroll
    for (int nt = 0; nt < 4; ++nt) {
        float bA = b2s[8 * nt + 2 * t4];
        float bB = b2s[8 * nt + 2 * t4 + 1];
        d0[nt] = bA; d1[nt] = bB; d2[nt] = bA; d3[nt] = bB;
    }
    {
        const uint32_t* h1u = &h1s[w][0];
        const ulonglong2* frs2 = reinterpret_cast<const ulonglong2*>(frs);
        const int xr = 4 * g4;             // (4*g4)&31, g4<8
        #pragma unroll 2
        for (int s = 0; s < 8; ++s) {
            int c0 = 8 * s + t4;
            uint32_t a0 = h1u[g4 * 64 + (c0 ^ xr)];
            uint32_t a1 = h1u[(g4 + 8) * 64 + (c0 ^ xr)];
            uint32_t a2 = h1u[g4 * 64 + ((c0 + 4) ^ xr)];
            uint32_t a3 = h1u[(g4 + 8) * 64 + ((c0 + 4) ^ xr)];
            ulonglong2 q0 = frs2[(s * 32 + lane) * 2 + 0];   // nt 0,1
            ulonglong2 q1 = frs2[(s * 32 + lane) * 2 + 1];   // nt 2,3
            uint32_t b0, b1v;
            asm("mov.b64 {%0,%1}, %2;" : "=r"(b0), "=r"(b1v) : "l"(q0.x));
            mma_tf32(d0[0], d1[0], d2[0], d3[0], a0, a1, a2, a3, b0, b1v);
            asm("mov.b64 {%0,%1}, %2;" : "=r"(b0), "=r"(b1v) : "l"(q0.y));
            mma_tf32(d0[1], d1[1], d2[1], d3[1], a0, a1, a2, a3, b0, b1v);
            asm("mov.b64 {%0,%1}, %2;" : "=r"(b0), "=r"(b1v) : "l"(q1.x));
            mma_tf32(d0[2], d1[2], d2[2], d3[2], a0, a1, a2, a3, b0, b1v);
            asm("mov.b64 {%0,%1}, %2;" : "=r"(b0), "=r"(b1v) : "l"(q1.y));
            mma_tf32(d0[3], d1[3], d2[3], d3[3], a0, a1, a2, a3, b0, b1v);
        }
    }

    // ---- epilogue: gelu, mean over 16 edges, write agg pairs ----
    const u64 HK2 = pack2(0.0625f, 0.0625f);
    #pragma unroll
    for (int nt = 0; nt < 4; ++nt) {
        u64 v = add2(gelu2(pack2(d0[nt], d1[nt])), gelu2(pack2(d2[nt], d3[nt])));
        v = add2(v, __shfl_xor_sync(0xffffffffu, v, 4));
        v = add2(v, __shfl_xor_sync(0xffffffffu, v, 8));
        v = add2(v, __shfl_xor_sync(0xffffffffu, v, 16));
        if (lane < 4) aggs[w][nt * 4 + lane] = mul2(v, HK2);
    }
    __syncwarp();

    // ---- out transform (packed) ----
    {
        const u64* ag = aggs[w];
        u64 acc2 = pack2(0.0f, 0.0f);
        #pragma unroll
        for (int i2 = 0; i2 < 16; ++i2)
            acc2 = fma2(ag[i2], __ldg(&g_W3p[i2 * 32 + lane]), acc2);
        float a0, a1; unpack2(acc2, a0, a1);
        float acc = __fadd_rn(__fadd_rn(a0, a1), b3s[lane]);
        out[(size_t)p * 32 + lane] = gelu_fast(acc);
    }
}

// ---------------------------------------------------------------------------
// launch
// ---------------------------------------------------------------------------
extern "C" void kernel_launch(void* const* d_in, const int* in_sizes, int n_in,
                              void* d_out, int out_size) {
    const float* gv = (const float*)d_in[0];
    const float* gf = (const float*)d_in[1];
    const float* pv = (const float*)d_in[2];
    const float* pf = (const float*)d_in[3];
    const float* W1 = (const float*)d_in[4];
    const float* b1 = (const float*)d_in[5];
    const float* W2 = (const float*)d_in[6];
    const float* b2 = (const float*)d_in[7];
    const float* W3 = (const float*)d_in[8];
    const float* b3 = (const float*)d_in[9];
    float* out = (float*)d_out;

    gpre_kernel<<<NGRID / 32, 256>>>(gf, W1, W2, W3);
    fused_kernel<<<NPTS / 8, 256>>>(gv, pv, pf, b1, b2, b3, out);
}